// round 5
// baseline (speedup 1.0000x reference)
#include <cuda_runtime.h>
#include <cuda_bf16.h>
#include <stdint.h>

#define FMAXV 3.4028235e38f

// ============================================================
// Device scratch (allocation-free). Split buffers: [2][rows][K] bf16
// plane 0 = bf16-hi, plane 1 = bf16(residual)
// ============================================================
__device__ __nv_bfloat16 g_xS  [2ull*4096*1024];
__device__ __nv_bfloat16 g_WKt [2ull*1024*1024];
__device__ __nv_bfloat16 g_WQt [2ull*1024*1024];
__device__ __nv_bfloat16 g_WVt [2ull*1024*1024];
__device__ __nv_bfloat16 g_Wot [2ull*1024*1024];
__device__ __nv_bfloat16 g_KS  [2ull*4096*1024];
__device__ __nv_bfloat16 g_QS  [2ull*4096*1024];
__device__ float         g_V   [4096ull*1024];
__device__ __nv_bfloat16 g_VtS [2ull*1024*4096];
__device__ __nv_bfloat16 g_attT[2ull*4096*4096];
__device__ __nv_bfloat16 g_YS  [2ull*4096*1024];
__device__ float         g_u   [1024];

// ============================================================
// Helpers (base sm_103-safe: mma.sync bf16 + cp.async only)
// ============================================================
__device__ __forceinline__ uint32_t smem_u32(const void* p) {
    uint32_t a;
    asm("{ .reg .u64 t; cvta.to.shared.u64 t, %1; cvt.u32.u64 %0, t; }" : "=r"(a) : "l"(p));
    return a;
}
__device__ __forceinline__ void cp16(void* s, const void* g) {
    uint32_t a = smem_u32(s);
    asm volatile("cp.async.cg.shared.global [%0], [%1], 16;" :: "r"(a), "l"(g));
}
#define CP_COMMIT()  asm volatile("cp.async.commit_group;" ::: "memory")
#define CP_WAIT(N)   asm volatile("cp.async.wait_group %0;" :: "n"(N) : "memory")

__device__ __forceinline__ void mma16(float* c, const uint32_t* a, const uint32_t* b) {
    asm volatile(
        "mma.sync.aligned.m16n8k16.row.col.f32.bf16.bf16.f32 "
        "{%0,%1,%2,%3}, {%4,%5,%6,%7}, {%8,%9}, {%0,%1,%2,%3};"
        : "+f"(c[0]), "+f"(c[1]), "+f"(c[2]), "+f"(c[3])
        : "r"(a[0]), "r"(a[1]), "r"(a[2]), "r"(a[3]), "r"(b[0]), "r"(b[1]));
}
__device__ __forceinline__ uint32_t split2_u32(float v0, float v1, uint32_t* lo) {
    __nv_bfloat16 h0 = __float2bfloat16_rn(v0);
    __nv_bfloat16 h1 = __float2bfloat16_rn(v1);
    __nv_bfloat16 l0 = __float2bfloat16_rn(v0 - __bfloat162float(h0));
    __nv_bfloat16 l1 = __float2bfloat16_rn(v1 - __bfloat162float(h1));
    *lo = (uint32_t)__bfloat16_as_ushort(l0) | ((uint32_t)__bfloat16_as_ushort(l1) << 16);
    return (uint32_t)__bfloat16_as_ushort(h0) | ((uint32_t)__bfloat16_as_ushort(h1) << 16);
}

// ============================================================
// GEMM: D[m,n] = sum_k A[m,k]*B[n,k]; A,B = 2-plane bf16 split.
// 3 products per K16: Ah*Bh + Ah*Bm + Am*Bh (mma m16n8k16 bf16).
// Tile 128x128, BK=16, 256 thr (8 warps, 64x32 warp tiles), 3-stage cp.async.
// EPI: 0 = bf16 split out, 1 = fp32 out, 3 = bf16 split out + uAdd vector
// SKIP: 1 = fully-masked logits tile -> return with NO writes
//       2 = attV: only K-chunks j < IB-129 (uniform rows via rank-1 uAdd)
// ============================================================
#define SROWH 24
#define BUF_H (128 * SROWH)
#define STAGE_H (4 * BUF_H)
#define NSTAGE 3
#define SMEM_DYN (NSTAGE * STAGE_H * 2)   // 73728 bytes

template <int EPI, int SKIP>
__global__ void __launch_bounds__(256, 2)
gemm_bf16(const __nv_bfloat16* __restrict__ A, const __nv_bfloat16* __restrict__ B,
          void* __restrict__ Cv, int lda, int ldb, int ldc,
          long long planeA, long long planeB, long long planeC,
          int nch, float alpha, const float* __restrict__ uAdd)
{
    const int tid = threadIdx.x;
    const int IB = blockIdx.y * 128;
    const int JB = blockIdx.x * 128;

    if (SKIP == 1 && (JB + 127 - IB) <= 256) return;   // masked tile: softmax never reads it

    extern __shared__ __nv_bfloat16 smh[];

    int T = nch;
    if (SKIP == 2) {
        int n1 = IB - 129; if (n1 < 0) n1 = 0;   // att col nonzero only for j < IB-129
        T = (n1 + 15) >> 4; if (T > nch) T = nch;
    }

    const int lane = tid & 31, w = tid >> 5;
    const int g = lane >> 2, tg = lane & 3;
    const int RW = (w >> 2) * 64, CW = (w & 3) * 32;

    auto issue = [&](int t) {
        int k0 = t * 16;
        __nv_bfloat16* sb = smh + (t % NSTAGE) * STAGE_H;
        #pragma unroll
        for (int r = 0; r < 4; r++) {
            int c = tid + r * 256;          // 0..1023
            int op = c >> 9;                 // 0=A, 1=B
            int rem = c & 511;
            int pl = rem >> 8;               // plane
            int rr = (rem & 255) >> 1;       // row 0..127
            int ck = rem & 1;                // 8-half chunk
            const __nv_bfloat16* src = (op ? B : A)
                + (size_t)pl * (op ? planeB : planeA)
                + (size_t)((op ? JB : IB) + rr) * (op ? ldb : lda) + k0 + ck * 8;
            __nv_bfloat16* dst = sb + op * 2 * BUF_H + pl * BUF_H + rr * SROWH + ck * 8;
            cp16(dst, src);
        }
        CP_COMMIT();
    };

    float acc[64];
    #pragma unroll
    for (int i = 0; i < 64; i++) acc[i] = 0.f;

    if (T > 0) issue(0);
    if (T > 1) issue(1);
    if (T > 2) issue(2);

    for (int t = 0; t < T; t++) {
        if (t + 2 < T) { CP_WAIT(2); } else if (t + 1 < T) { CP_WAIT(1); } else { CP_WAIT(0); }
        __syncthreads();

        const __nv_bfloat16* sb  = smh + (t % NSTAGE) * STAGE_H;
        const __nv_bfloat16* sAh = sb;
        const __nv_bfloat16* sAm = sb + BUF_H;
        const __nv_bfloat16* sBh = sb + 2 * BUF_H;
        const __nv_bfloat16* sBm = sb + 3 * BUF_H;

        uint32_t af[16], bh[8], bm[8];
        #pragma unroll
        for (int mt = 0; mt < 4; mt++) {
            const __nv_bfloat16* p = sAh + (RW + mt * 16 + g) * SROWH + 2 * tg;
            af[mt*4+0] = *(const uint32_t*)(p);
            af[mt*4+1] = *(const uint32_t*)(p + 8 * SROWH);
            af[mt*4+2] = *(const uint32_t*)(p + 8);
            af[mt*4+3] = *(const uint32_t*)(p + 8 * SROWH + 8);
        }
        #pragma unroll
        for (int nt = 0; nt < 4; nt++) {
            const __nv_bfloat16* p = sBh + (CW + nt * 8 + g) * SROWH + 2 * tg;
            bh[nt*2+0] = *(const uint32_t*)(p);
            bh[nt*2+1] = *(const uint32_t*)(p + 8);
        }
        #pragma unroll
        for (int mt = 0; mt < 4; mt++)
            #pragma unroll
            for (int nt = 0; nt < 4; nt++)
                mma16(&acc[(mt*4+nt)*4], &af[mt*4], &bh[nt*2]);
        #pragma unroll
        for (int nt = 0; nt < 4; nt++) {
            const __nv_bfloat16* p = sBm + (CW + nt * 8 + g) * SROWH + 2 * tg;
            bm[nt*2+0] = *(const uint32_t*)(p);
            bm[nt*2+1] = *(const uint32_t*)(p + 8);
        }
        #pragma unroll
        for (int mt = 0; mt < 4; mt++)
            #pragma unroll
            for (int nt = 0; nt < 4; nt++)
                mma16(&acc[(mt*4+nt)*4], &af[mt*4], &bm[nt*2]);
        #pragma unroll
        for (int mt = 0; mt < 4; mt++) {
            const __nv_bfloat16* p = sAm + (RW + mt * 16 + g) * SROWH + 2 * tg;
            af[mt*4+0] = *(const uint32_t*)(p);
            af[mt*4+1] = *(const uint32_t*)(p + 8 * SROWH);
            af[mt*4+2] = *(const uint32_t*)(p + 8);
            af[mt*4+3] = *(const uint32_t*)(p + 8 * SROWH + 8);
        }
        #pragma unroll
        for (int mt = 0; mt < 4; mt++)
            #pragma unroll
            for (int nt = 0; nt < 4; nt++)
                mma16(&acc[(mt*4+nt)*4], &af[mt*4], &bh[nt*2]);

        __syncthreads();
        if (t + 3 < T) issue(t + 3);
    }

    // ---------------- epilogue ----------------
    #pragma unroll
    for (int mt = 0; mt < 4; mt++) {
        #pragma unroll
        for (int nt = 0; nt < 4; nt++) {
            const float* cc = &acc[(mt*4+nt)*4];
            int r0 = IB + RW + mt * 16 + g;
            int c0 = JB + CW + nt * 8 + 2 * tg;
            float ux = 0.f, uy = 0.f;
            if (EPI == 3) { float2 uu = *(const float2*)(uAdd + c0); ux = uu.x; uy = uu.y; }
            #pragma unroll
            for (int half = 0; half < 2; half++) {
                int r = r0 + half * 8;
                float v0 = cc[half * 2 + 0] * alpha + ux;
                float v1 = cc[half * 2 + 1] * alpha + uy;
                if (EPI == 1) {
                    *(float2*)((float*)Cv + (size_t)r * ldc + c0) = make_float2(v0, v1);
                } else {
                    __nv_bfloat16* dst = (__nv_bfloat16*)Cv + (size_t)r * ldc + c0;
                    uint32_t lo;
                    uint32_t hi = split2_u32(v0, v1, &lo);
                    *(uint32_t*)dst            = hi;
                    *(uint32_t*)(dst + planeC) = lo;
                }
            }
        }
    }
}

// ============================================================
// Elementwise split to 2 bf16 planes (float4 vectorized)
// ============================================================
__global__ void __launch_bounds__(256)
split_kernel(const float* __restrict__ in, __nv_bfloat16* __restrict__ out, size_t S)
{
    size_t S4 = S >> 2;
    uint32_t* oh = (uint32_t*)out;
    uint32_t* ol = (uint32_t*)(out + S);
    for (size_t i4 = (size_t)blockIdx.x * blockDim.x + threadIdx.x; i4 < S4;
         i4 += (size_t)gridDim.x * blockDim.x) {
        float4 v = ((const float4*)in)[i4];
        uint32_t l0, l1;
        uint32_t h0 = split2_u32(v.x, v.y, &l0);
        uint32_t h1 = split2_u32(v.z, v.w, &l1);
        oh[i4 * 2] = h0; oh[i4 * 2 + 1] = h1;
        ol[i4 * 2] = l0; ol[i4 * 2 + 1] = l1;
    }
}

// ============================================================
// Transpose + split: in[R][C] fp32 -> out[2][C][R] bf16
// 64x64 tiles, 256 threads, float4 loads, packed bf16x2 stores.
// zlim: source rows r >= zlim are treated as ZERO (uniform att rows).
// MASKED=1 (att): tiles fully inside masked band or uniform band
//                 write zeros without reading.
// ============================================================
template <int MASKED>
__global__ void __launch_bounds__(256)
transpose_split64(const float* __restrict__ in, __nv_bfloat16* __restrict__ out,
                  int R, int C, int zlim)
{
    const int c0 = blockIdx.x * 64, r0 = blockIdx.y * 64;
    const int tid = threadIdx.x;
    const size_t plane = (size_t)R * C;
    const int oc = tid >> 2;            // output row (source col) 0..63
    const int rseg = (tid & 3) * 16;    // 16 source rows per thread

    if (MASKED && ((c0 + 63 - r0 <= 256) || (r0 >= 3840))) {
        uint32_t* d0 = (uint32_t*)(out + (size_t)(c0 + oc) * R + r0 + rseg);
        uint32_t* d1 = (uint32_t*)(out + plane + (size_t)(c0 + oc) * R + r0 + rseg);
        #pragma unroll
        for (int q = 0; q < 8; q++) { d0[q] = 0u; d1[q] = 0u; }
        return;
    }

    __shared__ float t[64][65];
    const int tr = tid >> 4;            // 0..15
    const int tc4 = (tid & 15) * 4;     // 0..60
    #pragma unroll
    for (int it = 0; it < 4; it++) {
        int rl = tr + it * 16;
        int r = r0 + rl;
        float4 v;
        if (MASKED && r >= zlim) v = make_float4(0.f, 0.f, 0.f, 0.f);
        else v = *(const float4*)&in[(size_t)r * C + c0 + tc4];
        t[rl][tc4 + 0] = v.x;
        t[rl][tc4 + 1] = v.y;
        t[rl][tc4 + 2] = v.z;
        t[rl][tc4 + 3] = v.w;
    }
    __syncthreads();

    uint32_t* d0 = (uint32_t*)(out + (size_t)(c0 + oc) * R + r0 + rseg);
    uint32_t* d1 = (uint32_t*)(out + plane + (size_t)(c0 + oc) * R + r0 + rseg);
    #pragma unroll
    for (int q = 0; q < 8; q++) {
        float v0 = t[rseg + 2 * q][oc];
        float v1 = t[rseg + 2 * q + 1][oc];
        uint32_t lo;
        uint32_t hi = split2_u32(v0, v1, &lo);
        d0[q] = hi; d1[q] = lo;
    }
}

// ============================================================
// rank-1 uniform-row correction: u[k] = (1/4096) * sum_{j>=3839} V[j][k]
// ============================================================
__global__ void __launch_bounds__(128)
rank1_kernel(const float* __restrict__ V, float* __restrict__ u)
{
    int k = blockIdx.x * 128 + threadIdx.x;   // grid 8 -> k in [0,1024)
    float s = 0.f;
    #pragma unroll 4
    for (int j = 3839; j < 4096; j++) s += V[(size_t)j * 1024 + k];
    u[k] = s * (1.0f / 4096.0f);
}

// ============================================================
// Structured row softmax (n=4096), one block per row, in-place.
// Row i: live cols j >= i+257. Reads only [s16, 4096) (head lanes
// substituted in-register), writes zeros below, normalized above.
// Rows i >= 3839: write exact 1/4096, zero reads.
// ============================================================
__global__ void __launch_bounds__(256)
softmax_kernel(float* __restrict__ att)
{
    const int i = blockIdx.x;
    const int tid = threadIdx.x;
    float* p = att + (size_t)i * 4096;

    if (i >= 3839) {
        const float c = 1.0f / 4096.0f;
        float4 cv = make_float4(c, c, c, c);
        #pragma unroll
        for (int q = 0; q < 4; q++) ((float4*)p)[tid + q * 256] = cv;
        return;
    }

    const int start = i + 257;
    const int s16 = start & ~15;
    const int nv4 = (4096 - s16) >> 2;
    float4* live = (float4*)(p + s16);

    float4 v[4];
    float mx = -FMAXV;
    #pragma unroll
    for (int q = 0; q < 4; q++) {
        int i4 = tid + q * 256;
        if (i4 < nv4) {
            float4 tv = live[i4];
            int j0 = s16 + i4 * 4;
            if (j0 < start) {   // head group: substitute masked lanes
                if (j0 + 0 < start) tv.x = -FMAXV;
                if (j0 + 1 < start) tv.y = -FMAXV;
                if (j0 + 2 < start) tv.z = -FMAXV;
                if (j0 + 3 < start) tv.w = -FMAXV;
            }
            v[q] = tv;
            mx = fmaxf(mx, fmaxf(fmaxf(tv.x, tv.y), fmaxf(tv.z, tv.w)));
        }
    }
    #pragma unroll
    for (int o = 16; o > 0; o >>= 1) mx = fmaxf(mx, __shfl_xor_sync(0xffffffffu, mx, o));
    __shared__ float red[8];
    if ((tid & 31) == 0) red[tid >> 5] = mx;
    __syncthreads();
    mx = red[0];
    #pragma unroll
    for (int ww = 1; ww < 8; ww++) mx = fmaxf(mx, red[ww]);
    __syncthreads();

    float s = 0.f;
    #pragma unroll
    for (int q = 0; q < 4; q++) {
        if (tid + q * 256 < nv4) {
            v[q].x = expf(v[q].x - mx); s += v[q].x;
            v[q].y = expf(v[q].y - mx); s += v[q].y;
            v[q].z = expf(v[q].z - mx); s += v[q].z;
            v[q].w = expf(v[q].w - mx); s += v[q].w;
        }
    }
    #pragma unroll
    for (int o = 16; o > 0; o >>= 1) s += __shfl_xor_sync(0xffffffffu, s, o);
    if ((tid & 31) == 0) red[tid >> 5] = s;
    __syncthreads();
    s = red[0];
    #pragma unroll
    for (int ww = 1; ww < 8; ww++) s += red[ww];

    float inv = 1.0f / s;
    #pragma unroll
    for (int q = 0; q < 4; q++) {
        int i4 = tid + q * 256;
        if (i4 < nv4) {
            v[q].x *= inv; v[q].y *= inv; v[q].z *= inv; v[q].w *= inv;
            live[i4] = v[q];
        }
    }
    // zero the masked head [0, s16)
    float4 z = make_float4(0.f, 0.f, 0.f, 0.f);
    int nz4 = s16 >> 2;
    for (int i4 = tid; i4 < nz4; i4 += 256) ((float4*)p)[i4] = z;
}

// ============================================================
// Host
// ============================================================
extern "C" void kernel_launch(void* const* d_in, const int* in_sizes, int n_in,
                              void* d_out, int out_size)
{
    const float* x    = (const float*)d_in[0];
    const float* WK   = (const float*)d_in[1];
    const float* WQ   = (const float*)d_in[2];
    const float* WV   = (const float*)d_in[3];
    const float* Wout = (const float*)d_in[4];

    const int m = 1024;
    const int n = in_sizes[0] / m;   // 4096

    float* y_out = (float*)d_out;                 // [n, m]
    float* att   = y_out + (size_t)n * m;         // [n, n]

    __nv_bfloat16 *pxS, *pWKt, *pWQt, *pWVt, *pWot, *pKS, *pQS, *pVt, *pattT, *pYS;
    float *pV, *pu;
    cudaGetSymbolAddress((void**)&pxS,  g_xS);
    cudaGetSymbolAddress((void**)&pWKt, g_WKt);
    cudaGetSymbolAddress((void**)&pWQt, g_WQt);
    cudaGetSymbolAddress((void**)&pWVt, g_WVt);
    cudaGetSymbolAddress((void**)&pWot, g_Wot);
    cudaGetSymbolAddress((void**)&pKS,  g_KS);
    cudaGetSymbolAddress((void**)&pQS,  g_QS);
    cudaGetSymbolAddress((void**)&pV,   g_V);
    cudaGetSymbolAddress((void**)&pVt,  g_VtS);
    cudaGetSymbolAddress((void**)&pattT, g_attT);
    cudaGetSymbolAddress((void**)&pYS,  g_YS);
    cudaGetSymbolAddress((void**)&pu,   g_u);

    cudaFuncSetAttribute(gemm_bf16<0, 0>, cudaFuncAttributeMaxDynamicSharedMemorySize, SMEM_DYN);
    cudaFuncSetAttribute(gemm_bf16<1, 0>, cudaFuncAttributeMaxDynamicSharedMemorySize, SMEM_DYN);
    cudaFuncSetAttribute(gemm_bf16<1, 1>, cudaFuncAttributeMaxDynamicSharedMemorySize, SMEM_DYN);
    cudaFuncSetAttribute(gemm_bf16<3, 2>, cudaFuncAttributeMaxDynamicSharedMemorySize, SMEM_DYN);

    const long long PX = 4096LL * 1024;  // x/K/Q/Y/Vt-sized plane (elements)
    const long long PW = 1024LL * 1024;  // weight plane
    const long long PA = 4096LL * 4096;  // attT plane
    const int BIG = 1 << 30;

    // Split x; transpose+split all weights
    split_kernel<<<2048, 256>>>(x, pxS, (size_t)n * m);
    transpose_split64<0><<<dim3(16, 16), 256>>>(WK,   pWKt, 1024, 1024, BIG);
    transpose_split64<0><<<dim3(16, 16), 256>>>(WQ,   pWQt, 1024, 1024, BIG);
    transpose_split64<0><<<dim3(16, 16), 256>>>(WV,   pWVt, 1024, 1024, BIG);
    transpose_split64<0><<<dim3(16, 16), 256>>>(Wout, pWot, 1024, 1024, BIG);

    // K = x@WK (split out), Q = 0.06*(x@WQ) (split out), V = x@WV (fp32)
    dim3 g1(8, 32);
    gemm_bf16<0, 0><<<g1, 256, SMEM_DYN>>>(pxS, pWKt, pKS, 1024, 1024, 1024, PX, PW, PX, 64, 1.0f, nullptr);
    gemm_bf16<0, 0><<<g1, 256, SMEM_DYN>>>(pxS, pWQt, pQS, 1024, 1024, 1024, PX, PW, PX, 64, 0.06f, nullptr);
    gemm_bf16<1, 0><<<g1, 256, SMEM_DYN>>>(pxS, pWVt, pV,  1024, 1024, 1024, PX, PW, 0,  64, 1.0f, nullptr);

    // logits = Q@K^T -> att (fp32 in d_out); fully-masked tiles untouched
    gemm_bf16<1, 1><<<dim3(32, 32), 256, SMEM_DYN>>>(pQS, pKS, att, 1024, 1024, 4096, PX, PX, 0, 64, 1.0f, nullptr);

    // structured softmax (writes zeros + normalized live region + uniform rows)
    softmax_kernel<<<n, 256>>>(att);

    // rank-1 uniform-row vector; V^T split; att^T split (uniform rows zeroed)
    rank1_kernel<<<8, 128>>>(pV, pu);
    transpose_split64<0><<<dim3(16, 64), 256>>>(pV,  pVt,   4096, 1024, BIG);
    transpose_split64<1><<<dim3(64, 64), 256>>>(att, pattT, 4096, 4096, 3839);

    // Y = att^T @ V (split out) with rank-1 add; K-chunks only j < IB-129
    gemm_bf16<3, 2><<<dim3(8, 32), 256, SMEM_DYN>>>(pattT, pVt, pYS, 4096, 4096, 1024, PA, PX, PX, 256, 1.0f, pu);

    // y_out = Y @ Wout (fp32)
    gemm_bf16<1, 0><<<dim3(8, 32), 256, SMEM_DYN>>>(pYS, pWot, y_out, 1024, 1024, 1024, PX, PW, 0, 64, 1.0f, nullptr);
}

// round 6
// speedup vs baseline: 1.4102x; 1.4102x over previous
#include <cuda_runtime.h>
#include <cuda_bf16.h>
#include <stdint.h>

#define FMAXV 3.4028235e38f

// ============================================================
// Device scratch (allocation-free). All split buffers: 2 bf16 planes
// (hi, residual) in the tensor's NATIVE layout — no transposes anywhere.
// ============================================================
__device__ __nv_bfloat16 g_xS  [2ull*4096*1024];   // [n][m]
__device__ __nv_bfloat16 g_WKs [2ull*1024*1024];   // [m][d]
__device__ __nv_bfloat16 g_WQs [2ull*1024*1024];
__device__ __nv_bfloat16 g_WVs [2ull*1024*1024];
__device__ __nv_bfloat16 g_Wos [2ull*1024*1024];   // [d][m]
__device__ __nv_bfloat16 g_KS  [2ull*4096*1024];   // [j][d]
__device__ __nv_bfloat16 g_QS  [2ull*4096*1024];   // [i][d]
__device__ __nv_bfloat16 g_VS  [2ull*4096*1024];   // [j][k]
__device__ __nv_bfloat16 g_attB[2ull*4096*4096];   // [r][a] (row-major, written by softmax)
__device__ __nv_bfloat16 g_YS  [2ull*4096*1024];   // [a][d]
__device__ float         g_u   [1024];

// ============================================================
// Helpers (base sm_103-safe: mma.sync bf16, cp.async, ldmatrix)
// ============================================================
__device__ __forceinline__ uint32_t smem_u32(const void* p) {
    uint32_t a;
    asm("{ .reg .u64 t; cvta.to.shared.u64 t, %1; cvt.u32.u64 %0, t; }" : "=r"(a) : "l"(p));
    return a;
}
__device__ __forceinline__ void cp16(void* s, const void* g) {
    uint32_t a = smem_u32(s);
    asm volatile("cp.async.cg.shared.global [%0], [%1], 16;" :: "r"(a), "l"(g));
}
#define CP_COMMIT()  asm volatile("cp.async.commit_group;" ::: "memory")
#define CP_WAIT(N)   asm volatile("cp.async.wait_group %0;" :: "n"(N) : "memory")

__device__ __forceinline__ void ldsm4(uint32_t* r, uint32_t a) {
    asm volatile("ldmatrix.sync.aligned.m8n8.x4.shared.b16 {%0,%1,%2,%3}, [%4];"
        : "=r"(r[0]), "=r"(r[1]), "=r"(r[2]), "=r"(r[3]) : "r"(a));
}
__device__ __forceinline__ void ldsm4t(uint32_t* r, uint32_t a) {
    asm volatile("ldmatrix.sync.aligned.m8n8.x4.trans.shared.b16 {%0,%1,%2,%3}, [%4];"
        : "=r"(r[0]), "=r"(r[1]), "=r"(r[2]), "=r"(r[3]) : "r"(a));
}
__device__ __forceinline__ void ldsm2(uint32_t* r, uint32_t a) {
    asm volatile("ldmatrix.sync.aligned.m8n8.x2.shared.b16 {%0,%1}, [%2];"
        : "=r"(r[0]), "=r"(r[1]) : "r"(a));
}
__device__ __forceinline__ void ldsm2t(uint32_t* r, uint32_t a) {
    asm volatile("ldmatrix.sync.aligned.m8n8.x2.trans.shared.b16 {%0,%1}, [%2];"
        : "=r"(r[0]), "=r"(r[1]) : "r"(a));
}
__device__ __forceinline__ void mma16(float* c, const uint32_t* a, const uint32_t* b) {
    asm volatile(
        "mma.sync.aligned.m16n8k16.row.col.f32.bf16.bf16.f32 "
        "{%0,%1,%2,%3}, {%4,%5,%6,%7}, {%8,%9}, {%0,%1,%2,%3};"
        : "+f"(c[0]), "+f"(c[1]), "+f"(c[2]), "+f"(c[3])
        : "r"(a[0]), "r"(a[1]), "r"(a[2]), "r"(a[3]), "r"(b[0]), "r"(b[1]));
}
__device__ __forceinline__ uint32_t split2_u32(float v0, float v1, uint32_t* lo) {
    __nv_bfloat16 h0 = __float2bfloat16_rn(v0);
    __nv_bfloat16 h1 = __float2bfloat16_rn(v1);
    __nv_bfloat16 l0 = __float2bfloat16_rn(v0 - __bfloat162float(h0));
    __nv_bfloat16 l1 = __float2bfloat16_rn(v1 - __bfloat162float(h1));
    *lo = (uint32_t)__bfloat16_as_ushort(l0) | ((uint32_t)__bfloat16_as_ushort(l1) << 16);
    return (uint32_t)__bfloat16_as_ushort(h0) | ((uint32_t)__bfloat16_as_ushort(h1) << 16);
}

// ============================================================
// GEMM: D[m,n] = sum_k A[m,k]*B[n,k]; A,B = 2-plane bf16 split.
// TRA=0: A global [M][K]; TRA=1: A global [K][M] (ldmatrix.trans).
// TRB=0: B global [N][K]; TRB=1: B global [K][N] (ldmatrix.trans).
// 3 products/K16: Ah*Bh + Ah*Bm + Am*Bh. Tile 128x128, BK=16,
// 256 thr (8 warps, 64x32), 4-stage cp.async, ONE barrier per chunk.
// EPI: 0 = bf16 split out, 1 = fp32 out, 3 = bf16 split out + uAdd
// SKIP: 1 = fully-masked logits tile -> return, no writes
//       2 = attV: K-chunks only j < IB-129 (uniform rows via rank-1)
// ============================================================
template <int TRA, int TRB, int EPI, int SKIP>
__global__ void __launch_bounds__(256, 2)
gemm_bf16(const __nv_bfloat16* __restrict__ A, const __nv_bfloat16* __restrict__ B,
          void* __restrict__ Cv, int lda, int ldb, int ldc,
          long long planeA, long long planeB, long long planeC,
          int nch, float alpha, const float* __restrict__ uAdd)
{
    constexpr int AROW = TRA ? 136 : 24;          // padded row strides (halves)
    constexpr int BROW = TRB ? 136 : 24;
    constexpr int APL  = TRA ? 16 * 136 : 128 * 24;
    constexpr int BPL  = TRB ? 16 * 136 : 128 * 24;
    constexpr int STG  = 2 * APL + 2 * BPL;       // Ah, Am, Bh, Bm (halves)

    const int tid = threadIdx.x;
    const int IB = blockIdx.y * 128;
    const int JB = blockIdx.x * 128;

    if (SKIP == 1 && (JB + 127 - IB) <= 256) return;

    extern __shared__ __nv_bfloat16 smh[];

    int T = nch;
    if (SKIP == 2) {
        int n1 = IB - 129; if (n1 < 0) n1 = 0;
        T = (n1 + 15) >> 4; if (T > nch) T = nch;
    }

    const int lane = tid & 31, w = tid >> 5;
    const int g = lane >> 2, tg = lane & 3; (void)g; (void)tg;
    const int RW = (w >> 2) * 64, CW = (w & 3) * 32;

    // ldmatrix per-lane offsets (halves within plane)
    const int lq = lane >> 3, li = lane & 7, q2 = lq & 1;
    int aoff, boff;
    if (TRA) aoff = ((lq >> 1) * 8 + li) * AROW + RW + (lq & 1) * 8;
    else     aoff = (RW + (lq & 1) * 8 + li) * AROW + (lq >> 1) * 8;
    if (TRB) boff = (q2 * 8 + li) * BROW + CW;
    else     boff = (CW + li) * BROW + q2 * 8;
    constexpr int AMT = TRA ? 16 : 16 * AROW;     // per-mt advance
    constexpr int BNT = TRB ? 8 : 8 * BROW;       // per-nt advance
    const uint32_t sb0 = smem_u32(smh);

    auto issue = [&](int t) {
        int k0 = t * 16;
        __nv_bfloat16* sb = smh + (t & 3) * STG;
        #pragma unroll
        for (int it = 0; it < 2; it++) {          // A: 2 planes
            int idx = tid + it * 256;
            int pl = idx >> 8, r = idx & 255;
            __nv_bfloat16* dst; const __nv_bfloat16* src;
            if (TRA) { int row = r >> 4, ch = r & 15;
                dst = sb + pl * APL + row * AROW + ch * 8;
                src = A + (size_t)pl * planeA + (size_t)(k0 + row) * lda + IB + ch * 8;
            } else { int row = r >> 1, ch = r & 1;
                dst = sb + pl * APL + row * AROW + ch * 8;
                src = A + (size_t)pl * planeA + (size_t)(IB + row) * lda + k0 + ch * 8;
            }
            cp16(dst, src);
        }
        #pragma unroll
        for (int it = 0; it < 2; it++) {          // B: 2 planes
            int idx = tid + it * 256;
            int pl = idx >> 8, r = idx & 255;
            __nv_bfloat16* dst; const __nv_bfloat16* src;
            if (TRB) { int row = r >> 4, ch = r & 15;
                dst = sb + 2 * APL + pl * BPL + row * BROW + ch * 8;
                src = B + (size_t)pl * planeB + (size_t)(k0 + row) * ldb + JB + ch * 8;
            } else { int row = r >> 1, ch = r & 1;
                dst = sb + 2 * APL + pl * BPL + row * BROW + ch * 8;
                src = B + (size_t)pl * planeB + (size_t)(JB + row) * ldb + k0 + ch * 8;
            }
            cp16(dst, src);
        }
        CP_COMMIT();
    };

    float acc[64];
    #pragma unroll
    for (int i = 0; i < 64; i++) acc[i] = 0.f;

    if (T > 0) issue(0);
    if (T > 1) issue(1);
    if (T > 2) issue(2);

    for (int t = 0; t < T; t++) {
        if (t + 2 < T) { CP_WAIT(2); } else if (t + 1 < T) { CP_WAIT(1); } else { CP_WAIT(0); }
        __syncthreads();

        uint32_t sbb = sb0 + (uint32_t)((t & 3) * STG) * 2;
        uint32_t aH = sbb + (uint32_t)aoff * 2;
        uint32_t aM = aH + APL * 2;
        uint32_t bHa = sbb + (uint32_t)(2 * APL + boff) * 2;
        uint32_t bMa = bHa + BPL * 2;

        uint32_t af[16], am[16], bh[8], bm[8];
        #pragma unroll
        for (int mt = 0; mt < 4; mt++) {
            if (TRA) ldsm4t(af + mt * 4, aH + mt * AMT * 2);
            else     ldsm4 (af + mt * 4, aH + mt * AMT * 2);
        }
        #pragma unroll
        for (int nt = 0; nt < 4; nt++) {
            if (TRB) ldsm2t(bh + nt * 2, bHa + nt * BNT * 2);
            else     ldsm2 (bh + nt * 2, bHa + nt * BNT * 2);
        }
        #pragma unroll
        for (int mt = 0; mt < 4; mt++)
            #pragma unroll
            for (int nt = 0; nt < 4; nt++)
                mma16(&acc[(mt * 4 + nt) * 4], af + mt * 4, bh + nt * 2);
        #pragma unroll
        for (int nt = 0; nt < 4; nt++) {
            if (TRB) ldsm2t(bm + nt * 2, bMa + nt * BNT * 2);
            else     ldsm2 (bm + nt * 2, bMa + nt * BNT * 2);
        }
        #pragma unroll
        for (int mt = 0; mt < 4; mt++)
            #pragma unroll
            for (int nt = 0; nt < 4; nt++)
                mma16(&acc[(mt * 4 + nt) * 4], af + mt * 4, bm + nt * 2);
        #pragma unroll
        for (int mt = 0; mt < 4; mt++) {
            if (TRA) ldsm4t(am + mt * 4, aM + mt * AMT * 2);
            else     ldsm4 (am + mt * 4, aM + mt * AMT * 2);
        }
        #pragma unroll
        for (int mt = 0; mt < 4; mt++)
            #pragma unroll
            for (int nt = 0; nt < 4; nt++)
                mma16(&acc[(mt * 4 + nt) * 4], am + mt * 4, bh + nt * 2);

        if (t + 3 < T) issue(t + 3);   // writes stage (t-1)&3, freed by top barrier
    }

    // ---------------- epilogue ----------------
    const int eg = lane >> 2, etg = lane & 3;
    #pragma unroll
    for (int mt = 0; mt < 4; mt++) {
        #pragma unroll
        for (int nt = 0; nt < 4; nt++) {
            const float* cc = &acc[(mt * 4 + nt) * 4];
            int r0 = IB + RW + mt * 16 + eg;
            int c0 = JB + CW + nt * 8 + 2 * etg;
            float ux = 0.f, uy = 0.f;
            if (EPI == 3) { float2 uu = *(const float2*)(uAdd + c0); ux = uu.x; uy = uu.y; }
            #pragma unroll
            for (int half = 0; half < 2; half++) {
                int r = r0 + half * 8;
                float v0 = cc[half * 2 + 0] * alpha + ux;
                float v1 = cc[half * 2 + 1] * alpha + uy;
                if (EPI == 1) {
                    *(float2*)((float*)Cv + (size_t)r * ldc + c0) = make_float2(v0, v1);
                } else {
                    __nv_bfloat16* dst = (__nv_bfloat16*)Cv + (size_t)r * ldc + c0;
                    uint32_t lo;
                    uint32_t hi = split2_u32(v0, v1, &lo);
                    *(uint32_t*)dst            = hi;
                    *(uint32_t*)(dst + planeC) = lo;
                }
            }
        }
    }
}

// ============================================================
// Elementwise split to 2 bf16 planes (float4 vectorized)
// ============================================================
__global__ void __launch_bounds__(256)
split_kernel(const float* __restrict__ in, __nv_bfloat16* __restrict__ out, size_t S)
{
    size_t S4 = S >> 2;
    uint32_t* oh = (uint32_t*)out;
    uint32_t* ol = (uint32_t*)(out + S);
    for (size_t i4 = (size_t)blockIdx.x * blockDim.x + threadIdx.x; i4 < S4;
         i4 += (size_t)gridDim.x * blockDim.x) {
        float4 v = ((const float4*)in)[i4];
        uint32_t l0, l1;
        uint32_t h0 = split2_u32(v.x, v.y, &l0);
        uint32_t h1 = split2_u32(v.z, v.w, &l1);
        oh[i4 * 2] = h0; oh[i4 * 2 + 1] = h1;
        ol[i4 * 2] = l0; ol[i4 * 2 + 1] = l1;
    }
}

// ============================================================
// rank-1 uniform-row correction from V bf16 planes:
// u[k] = (1/4096) * sum_{j>=3839} (Vh+Vl)[j][k]
// ============================================================
__global__ void __launch_bounds__(128)
rank1_kernel(const __nv_bfloat16* __restrict__ Vp, float* __restrict__ u)
{
    int k = blockIdx.x * 128 + threadIdx.x;   // grid 8
    const __nv_bfloat16* Vh = Vp;
    const __nv_bfloat16* Vl = Vp + 4096ull * 1024;
    float s = 0.f;
    #pragma unroll 4
    for (int j = 3839; j < 4096; j++) {
        size_t o = (size_t)j * 1024 + k;
        s += __bfloat162float(Vh[o]) + __bfloat162float(Vl[o]);
    }
    u[k] = s * (1.0f / 4096.0f);
}

// ============================================================
// Structured softmax + fused bf16 split, one block per row.
// Row i < 3839: live cols j >= i+257; writes fp32 att row (zero head +
// normalized live) AND bf16 hi/lo planes row-major (no transpose needed:
// attV consumes [r][a] via ldmatrix.trans).
// Rows i >= 3839: fp32 = 1/4096 exactly, bf16 planes = 0 (rank-1 handles them).
// ============================================================
__global__ void __launch_bounds__(256)
softmax_split(float* __restrict__ att, __nv_bfloat16* __restrict__ ab, long long PA)
{
    const int i = blockIdx.x;
    const int tid = threadIdx.x;
    float* p = att + (size_t)i * 4096;
    __nv_bfloat16* bhp = ab + (size_t)i * 4096;
    __nv_bfloat16* blp = bhp + PA;

    if (i >= 3839) {
        const float c = 1.0f / 4096.0f;
        float4 cv = make_float4(c, c, c, c);
        #pragma unroll
        for (int q = 0; q < 4; q++) ((float4*)p)[tid + q * 256] = cv;
        uint4 z = make_uint4(0, 0, 0, 0);
        #pragma unroll
        for (int q = 0; q < 2; q++) {
            ((uint4*)bhp)[tid + q * 256] = z;
            ((uint4*)blp)[tid + q * 256] = z;
        }
        return;
    }

    const int start = i + 257;
    const int s16 = start & ~15;
    const int nv4 = (4096 - s16) >> 2;
    float4* live = (float4*)(p + s16);

    float4 v[4];
    float mx = -FMAXV;
    #pragma unroll
    for (int q = 0; q < 4; q++) {
        int i4 = tid + q * 256;
        if (i4 < nv4) {
            float4 tv = live[i4];
            int j0 = s16 + i4 * 4;
            if (j0 < start) {
                if (j0 + 0 < start) tv.x = -FMAXV;
                if (j0 + 1 < start) tv.y = -FMAXV;
                if (j0 + 2 < start) tv.z = -FMAXV;
                if (j0 + 3 < start) tv.w = -FMAXV;
            }
            v[q] = tv;
            mx = fmaxf(mx, fmaxf(fmaxf(tv.x, tv.y), fmaxf(tv.z, tv.w)));
        }
    }
    #pragma unroll
    for (int o = 16; o > 0; o >>= 1) mx = fmaxf(mx, __shfl_xor_sync(0xffffffffu, mx, o));
    __shared__ float red[8];
    if ((tid & 31) == 0) red[tid >> 5] = mx;
    __syncthreads();
    mx = red[0];
    #pragma unroll
    for (int ww = 1; ww < 8; ww++) mx = fmaxf(mx, red[ww]);
    __syncthreads();

    float s = 0.f;
    #pragma unroll
    for (int q = 0; q < 4; q++) {
        if (tid + q * 256 < nv4) {
            v[q].x = expf(v[q].x - mx); s += v[q].x;
            v[q].y = expf(v[q].y - mx); s += v[q].y;
            v[q].z = expf(v[q].z - mx); s += v[q].z;
            v[q].w = expf(v[q].w - mx); s += v[q].w;
        }
    }
    #pragma unroll
    for (int o = 16; o > 0; o >>= 1) s += __shfl_xor_sync(0xffffffffu, s, o);
    if ((tid & 31) == 0) red[tid >> 5] = s;
    __syncthreads();
    s = red[0];
    #pragma unroll
    for (int ww = 1; ww < 8; ww++) s += red[ww];

    float inv = 1.0f / s;
    uint2* bhl = (uint2*)(bhp + s16);
    uint2* bll = (uint2*)(blp + s16);
    #pragma unroll
    for (int q = 0; q < 4; q++) {
        int i4 = tid + q * 256;
        if (i4 < nv4) {
            v[q].x *= inv; v[q].y *= inv; v[q].z *= inv; v[q].w *= inv;
            live[i4] = v[q];
            uint32_t l0, l1;
            uint32_t h0 = split2_u32(v[q].x, v[q].y, &l0);
            uint32_t h1 = split2_u32(v[q].z, v[q].w, &l1);
            bhl[i4] = make_uint2(h0, h1);
            bll[i4] = make_uint2(l0, l1);
        }
    }
    // zero heads
    float4 z4 = make_float4(0.f, 0.f, 0.f, 0.f);
    int nz4 = s16 >> 2;
    for (int i4 = tid; i4 < nz4; i4 += 256) ((float4*)p)[i4] = z4;
    uint2 z2 = make_uint2(0, 0);
    for (int i2 = tid; i2 < nz4; i2 += 256) {
        ((uint2*)bhp)[i2] = z2;
        ((uint2*)blp)[i2] = z2;
    }
}

// ============================================================
// Host
// ============================================================
extern "C" void kernel_launch(void* const* d_in, const int* in_sizes, int n_in,
                              void* d_out, int out_size)
{
    const float* x    = (const float*)d_in[0];
    const float* WK   = (const float*)d_in[1];
    const float* WQ   = (const float*)d_in[2];
    const float* WV   = (const float*)d_in[3];
    const float* Wout = (const float*)d_in[4];

    const int m = 1024;
    const int n = in_sizes[0] / m;   // 4096

    float* y_out = (float*)d_out;                 // [n, m]
    float* att   = y_out + (size_t)n * m;         // [n, n]

    __nv_bfloat16 *pxS, *pWK, *pWQ, *pWV, *pWo, *pKS, *pQS, *pVS, *pattB, *pYS;
    float* pu;
    cudaGetSymbolAddress((void**)&pxS,  g_xS);
    cudaGetSymbolAddress((void**)&pWK,  g_WKs);
    cudaGetSymbolAddress((void**)&pWQ,  g_WQs);
    cudaGetSymbolAddress((void**)&pWV,  g_WVs);
    cudaGetSymbolAddress((void**)&pWo,  g_Wos);
    cudaGetSymbolAddress((void**)&pKS,  g_KS);
    cudaGetSymbolAddress((void**)&pQS,  g_QS);
    cudaGetSymbolAddress((void**)&pVS,  g_VS);
    cudaGetSymbolAddress((void**)&pattB, g_attB);
    cudaGetSymbolAddress((void**)&pYS,  g_YS);
    cudaGetSymbolAddress((void**)&pu,   g_u);

    // dynamic smem sizes per instantiation (4 stages)
    const int SM01 = 4 * (2 * (128 * 24) + 2 * (16 * 136)) * 2;  // TRA0,TRB1: 83968
    const int SM00 = 4 * (4 * (128 * 24)) * 2;                   // TRA0,TRB0: 98304
    const int SM11 = 4 * (4 * (16 * 136)) * 2;                   // TRA1,TRB1: 69632

    cudaFuncSetAttribute(gemm_bf16<0, 1, 0, 0>, cudaFuncAttributeMaxDynamicSharedMemorySize, SM01);
    cudaFuncSetAttribute(gemm_bf16<0, 0, 1, 1>, cudaFuncAttributeMaxDynamicSharedMemorySize, SM00);
    cudaFuncSetAttribute(gemm_bf16<1, 1, 3, 2>, cudaFuncAttributeMaxDynamicSharedMemorySize, SM11);
    cudaFuncSetAttribute(gemm_bf16<0, 1, 1, 0>, cudaFuncAttributeMaxDynamicSharedMemorySize, SM01);

    const long long PX = 4096LL * 1024;
    const long long PW = 1024LL * 1024;
    const long long PA = 4096LL * 4096;

    // Elementwise splits only — NO transposes.
    split_kernel<<<2048, 256>>>(x,    pxS, (size_t)n * m);
    split_kernel<<<512,  256>>>(WK,   pWK, (size_t)m * m);
    split_kernel<<<512,  256>>>(WQ,   pWQ, (size_t)m * m);
    split_kernel<<<512,  256>>>(WV,   pWV, (size_t)m * m);
    split_kernel<<<512,  256>>>(Wout, pWo, (size_t)m * m);

    // K/Q/V = x@W  (A=[M][K] normal, B=[K][N] trans) -> bf16 split out
    dim3 g1(8, 32);
    gemm_bf16<0, 1, 0, 0><<<g1, 256, SM01>>>(pxS, pWK, pKS, 1024, 1024, 1024, PX, PW, PX, 64, 1.0f, nullptr);
    gemm_bf16<0, 1, 0, 0><<<g1, 256, SM01>>>(pxS, pWQ, pQS, 1024, 1024, 1024, PX, PW, PX, 64, 0.06f, nullptr);
    gemm_bf16<0, 1, 0, 0><<<g1, 256, SM01>>>(pxS, pWV, pVS, 1024, 1024, 1024, PX, PW, PX, 64, 1.0f, nullptr);

    // logits = Q@K^T (A=[M][K] normal, B=[N][K] normal) -> fp32 att in d_out
    gemm_bf16<0, 0, 1, 1><<<dim3(32, 32), 256, SM00>>>(pQS, pKS, att, 1024, 1024, 4096, PX, PX, 0, 64, 1.0f, nullptr);

    // softmax + fused bf16 split (row-major planes)
    softmax_split<<<n, 256>>>(att, pattB, PA);

    // rank-1 uniform-row vector from V planes
    rank1_kernel<<<8, 128>>>(pVS, pu);

    // Y = att^T @ V  (A=att [K][M] trans, B=V [K][N] trans) + rank-1 add
    gemm_bf16<1, 1, 3, 2><<<dim3(8, 32), 256, SM11>>>(pattB, pVS, pYS, 4096, 1024, 1024, PA, PX, PX, 256, 1.0f, pu);

    // y_out = Y @ Wout (A=[M][K] normal, B=[K][N] trans) -> fp32
    gemm_bf16<0, 1, 1, 0><<<g1, 256, SM01>>>(pYS, pWo, y_out, 1024, 1024, 1024, PX, PW, 0, 64, 1.0f, nullptr);
}